// round 7
// baseline (speedup 1.0000x reference)
#include <cuda_runtime.h>
#include <cstdint>
#include <cstddef>

// ---------------------------------------------------------------------------
// Spiking conv + WTA, Round 7: pre-binarized input bitmasks, delta^2 event
// scatter through a 50-row x 3-pass reused grid, registerized WTA records.
// One 32-thread CTA per (b,ox,oy); lane = output channel.
//   r(tau) = tau/16 - (3/32) relu(tau-16w) + (1/32) relu(tau-48w)   (exact)
// ---------------------------------------------------------------------------

#define COUT   32
#define W18    18
#define KS     48
#define TIN    100
#define TOUT   149
#define NSPAT  31
#define THETA  5.4f
#define WROWS  50          // grid rows per pass
#define NPASS  3

// event tables, layout [w][o]
__device__ float4   g_t1[W18 * COUT];   // ev1a, ev1b, ev2a, ev2b
__device__ int      g_t2[W18 * COUT];   // n1 | (n2<<16)
__device__ unsigned g_bits[16 * 2 * 64 * 64 * 4];   // spike bitmasks, 2 MB

__global__ void evt_precompute(const float* __restrict__ weight) {
    int idx = blockIdx.x * blockDim.x + threadIdx.x;
    if (idx >= W18 * COUT) return;
    int o = idx & 31;
    int w = idx >> 5;
    double wv = (double)weight[o * W18 + w];

    double p1 = 16.0 * wv;                    // peak knot
    int    n1 = (int)floor(p1) + 1;
    double f1 = (double)n1 - p1;              // in (0,1]
    const double c1 = -3.0 / 32.0;
    double p2 = 48.0 * wv;                    // zero-cross knot
    int    n2 = (int)floor(p2) + 1;
    double f2 = (double)n2 - p2;
    const double c2 = 1.0 / 32.0;

    g_t1[idx] = make_float4((float)(c1 * f1), (float)(c1 * (1.0 - f1)),
                            (float)(c2 * f2), (float)(c2 * (1.0 - f2)));
    g_t2[idx] = n1 | (n2 << 16);
}

__global__ __launch_bounds__(256)
void binarize_kernel(const float* __restrict__ xin) {
    int wg   = (blockIdx.x * blockDim.x + threadIdx.x) >> 5;
    int lane = threadIdx.x & 31;
    if (wg >= 16 * 2 * 64 * 64) return;
    const float* row = xin + (size_t)wg * TIN;
    unsigned m[4];
#pragma unroll
    for (int seg = 0; seg < 4; ++seg) {
        int t = seg * 32 + lane;
        float v = (t < TIN) ? __ldg(row + t) : 0.f;
        m[seg] = __ballot_sync(0xffffffffu, v != 0.f);
    }
    if (lane == 0)
        *(uint4*)&g_bits[(size_t)wg * 4] = make_uint4(m[0], m[1], m[2], m[3]);
}

// Neumaier compensated add: s += v, compensation c
__device__ __forceinline__ void kadd(float& s, float& c, float v) {
    float t = s + v;
    float e = (fabsf(s) >= fabsf(v)) ? ((s - t) + v) : ((v - t) + s);
    c += e;
    s = t;
}

__global__ __launch_bounds__(32)
void wta_kernel(float* __restrict__ out) {
    __shared__ float4             s_grid4[WROWS * COUT / 4];   // 6400 B reused
    __shared__ float              s_cnt[152];                  // ramp d2
    __shared__ __align__(16) unsigned s_bits[72];              // 18 rows x 4

    float* s_grid = (float*)s_grid4;

    const int lane = threadIdx.x;
    const int bx   = blockIdx.x;                     // n = ox*31 + oy
    const int b    = blockIdx.y;
    const int ox   = bx / NSPAT;
    const int oy   = bx - ox * NSPAT;

    // ---- stage 1: fetch 18 bitmask rows (one LDG.128 per active lane) ----
    if (lane < W18) {
        int i = lane / 9, rem = lane - i * 9, kx = rem / 3, ky = rem - kx * 3;
        size_t rowidx = (((size_t)b * 2 + i) * 64 + (2 * ox + kx)) * 64 + (2 * oy + ky);
        uint4 v = __ldg((const uint4*)&g_bits[rowidx * 4]);
        *(uint4*)&s_bits[lane * 4] = v;
    }
#pragma unroll
    for (int i = lane; i < 152; i += 32) s_cnt[i] = 0.f;
    __syncwarp();

    // ---- stage 1b: shared-ramp counts: cnt[s+2] = (#spikes at s)/16 ----
#pragma unroll
    for (int seg = 0; seg < 4; ++seg) {
        int c = 0;
#pragma unroll
        for (int w = 0; w < W18; ++w) c += (int)((s_bits[w * 4 + seg] >> lane) & 1u);
        int s = seg * 32 + lane;
        if (s < TIN) s_cnt[s + 2] = (float)c * 0.0625f;
    }
    __syncwarp();

    // ---- per-pass: zero grid, scatter events, cumsum + WTA ----
    float* col = s_grid + lane;
    float a1 = 0.f, c1 = 0.f, a2 = 0.f;
    int dep = 0, k = 0;
    int wt0 = -1, wt1 = -1, wt2 = -1, wt3 = -1;
    int wc0 = 0, wc1 = 0, wc2 = 0, wc3 = 0;

#pragma unroll 1
    for (int h = 0; h < NPASS; ++h) {
        const int lo = h * WROWS;

        // zero grid
        {
            float4 z4 = make_float4(0.f, 0.f, 0.f, 0.f);
#pragma unroll
            for (int i = lane; i < WROWS * COUT / 4; i += 32) s_grid4[i] = z4;
        }
        __syncwarp();

        // seg masks: spike s relevant iff s in [lo-50, lo+47]
        const int smin = lo - 50 < 0 ? 0 : lo - 50;
        const int smax = lo + 47;
        unsigned segmask[4];
#pragma unroll
        for (int seg = 0; seg < 4; ++seg) {
            int loR = smin - seg * 32, hiR = smax - seg * 32;
            unsigned mk = 0u;
            if (hiR >= 0 && loR <= 31) {
                unsigned hm = (hiR >= 31) ? 0xffffffffu : ((1u << (hiR + 1)) - 1u);
                unsigned lm = (loR <= 0)  ? 0xffffffffu : ~((1u << loR) - 1u);
                mk = hm & lm;
            }
            segmask[seg] = mk;
        }

        // scatter hinge events (lane-private smem column, deterministic order)
#pragma unroll 1
        for (int w = 0; w < W18; ++w) {
            float4 ev = __ldg(&g_t1[w * 32 + lane]);
            int    nn = __ldg(&g_t2[w * 32 + lane]);
            int n1 = nn & 0xffff;
            int n2 = nn >> 16;
#pragma unroll
            for (int seg = 0; seg < 4; ++seg) {
                unsigned m = s_bits[w * 4 + seg] & segmask[seg];
                int sbase = seg * 32 + 1 - lo;       // r - lo for bit 0
                while (m) {
                    int bp = __ffs((int)m) - 1;
                    m &= m - 1;
                    int r1 = sbase + bp + n1;
                    int r2 = sbase + bp + n2;
                    if ((unsigned)r1 < (unsigned)WROWS)       col[r1 * 32]       += ev.x;
                    if ((unsigned)(r1 + 1) < (unsigned)WROWS) col[(r1 + 1) * 32] += ev.y;
                    if ((unsigned)r2 < (unsigned)WROWS)       col[r2 * 32]       += ev.z;
                    if ((unsigned)(r2 + 1) < (unsigned)WROWS) col[(r2 + 1) * 32] += ev.w;
                }
            }
        }
        __syncwarp();

        // double cumsum + ballot-gated WTA over this pass's t range
        const int tend = (lo + WROWS < TOUT) ? lo + WROWS : TOUT;
#pragma unroll 1
        for (int t = lo; t < tend; ++t) {
            float v = s_grid[(t - lo) * 32 + lane] + s_cnt[t];
            kadd(a1, c1, v);
            a2 += (a1 + c1);
            if (dep == 0) {
                unsigned fm = __ballot_sync(0xffffffffu, a2 > THETA);
                if (fm) {
                    float bv = a2; int bi = lane;
#pragma unroll
                    for (int off = 16; off; off >>= 1) {
                        float ov = __shfl_xor_sync(0xffffffffu, bv, off);
                        int   oi = __shfl_xor_sync(0xffffffffu, bi, off);
                        if (ov > bv || (ov == bv && oi < bi)) { bv = ov; bi = oi; }
                    }
                    if      (k == 0) { wt0 = t; wc0 = bi; }
                    else if (k == 1) { wt1 = t; wc1 = bi; }
                    else if (k == 2) { wt2 = t; wc2 = bi; }
                    else             { wt3 = t; wc3 = bi; }
                    ++k;
                    dep = KS;
                }
            }
            dep = dep > 0 ? dep - 1 : 0;
        }
        __syncwarp();
    }

    // ---- output: every element written, coalesced 128B per (oc, q) ----
#pragma unroll
    for (int q = 0; q < 5; ++q) {
        int t = q * 32 + lane;
        if (t < TOUT) {
            int wv = -1;
            if (t == wt0) wv = wc0;
            if (t == wt1) wv = wc1;
            if (t == wt2) wv = wc2;
            if (t == wt3) wv = wc3;
            float* obase = out + ((size_t)b * 32 * (NSPAT * NSPAT) + bx) * TOUT + t;
#pragma unroll 1
            for (int oc = 0; oc < 32; ++oc)
                obase[(size_t)oc * (NSPAT * NSPAT) * TOUT] = (wv == oc) ? 1.f : 0.f;
        }
    }
}

extern "C" void kernel_launch(void* const* d_in, const int* in_sizes, int n_in,
                              void* d_out, int out_size) {
    const float* spikes = (const float*)d_in[0];
    const float* weight = (const float*)d_in[1];
    if (n_in >= 2 && in_sizes[0] == 576) {     // defensive input identification
        spikes = (const float*)d_in[1];
        weight = (const float*)d_in[0];
    }

    evt_precompute<<<3, 192>>>(weight);
    binarize_kernel<<<16 * 2 * 64 * 64 / 8, 256>>>(spikes);

    dim3 grid(NSPAT * NSPAT, 16);   // (n, batch)
    wta_kernel<<<grid, 32>>>((float*)d_out);
}

// round 8
// speedup vs baseline: 1.0211x; 1.0211x over previous
#include <cuda_runtime.h>
#include <cstdint>
#include <cstddef>

// ---------------------------------------------------------------------------
// Spiking conv + WTA, Round 8: round-6 structure (76-row x 2-pass delta^2
// grid) + pre-binarized input bitmasks + registerized WTA records.
// One 32-thread CTA per (b,ox,oy); lane = output channel.
//   r(tau) = tau/16 - (3/32) relu(tau-16w) + (1/32) relu(tau-48w)   (exact)
// ---------------------------------------------------------------------------

#define COUT   32
#define W18    18
#define KS     48
#define TIN    100
#define TOUT   149
#define NSPAT  31
#define THETA  5.4f
#define HROWS  76          // grid rows per pass (2 passes cover 152)

// event tables, layout [w][o]
__device__ float4   g_t1[W18 * COUT];   // ev1a, ev1b, ev2a, ev2b
__device__ int      g_t2[W18 * COUT];   // n1 | (n2<<16)
__device__ unsigned g_bits[16 * 2 * 64 * 64 * 4];   // spike bitmasks, 2 MB

__global__ void evt_precompute(const float* __restrict__ weight) {
    int idx = blockIdx.x * blockDim.x + threadIdx.x;
    if (idx >= W18 * COUT) return;
    int o = idx & 31;
    int w = idx >> 5;
    double wv = (double)weight[o * W18 + w];

    double p1 = 16.0 * wv;                    // peak knot
    int    n1 = (int)floor(p1) + 1;
    double f1 = (double)n1 - p1;              // in (0,1]
    const double c1 = -3.0 / 32.0;
    double p2 = 48.0 * wv;                    // zero-cross knot
    int    n2 = (int)floor(p2) + 1;
    double f2 = (double)n2 - p2;
    const double c2 = 1.0 / 32.0;

    g_t1[idx] = make_float4((float)(c1 * f1), (float)(c1 * (1.0 - f1)),
                            (float)(c2 * f2), (float)(c2 * (1.0 - f2)));
    g_t2[idx] = n1 | (n2 << 16);
}

__global__ __launch_bounds__(256)
void binarize_kernel(const float* __restrict__ xin) {
    int wg   = (blockIdx.x * blockDim.x + threadIdx.x) >> 5;
    int lane = threadIdx.x & 31;
    if (wg >= 16 * 2 * 64 * 64) return;
    const float* row = xin + (size_t)wg * TIN;
    unsigned m[4];
#pragma unroll
    for (int seg = 0; seg < 4; ++seg) {
        int t = seg * 32 + lane;
        float v = (t < TIN) ? __ldg(row + t) : 0.f;
        m[seg] = __ballot_sync(0xffffffffu, v != 0.f);
    }
    if (lane == 0)
        *(uint4*)&g_bits[(size_t)wg * 4] = make_uint4(m[0], m[1], m[2], m[3]);
}

// Neumaier compensated add: s += v, compensation c
__device__ __forceinline__ void kadd(float& s, float& c, float v) {
    float t = s + v;
    float e = (fabsf(s) >= fabsf(v)) ? ((s - t) + v) : ((v - t) + s);
    c += e;
    s = t;
}

__global__ __launch_bounds__(32)
void wta_kernel(float* __restrict__ out) {
    __shared__ float4                 s_grid4[HROWS * COUT / 4]; // 9728 B reused
    __shared__ float                  s_cnt[152];                // ramp d2
    __shared__ __align__(16) unsigned s_bits[72];                // 18 rows x 4

    float* s_grid = (float*)s_grid4;

    const int lane = threadIdx.x;
    const int bx   = blockIdx.x;                     // n = ox*31 + oy
    const int b    = blockIdx.y;
    const int ox   = bx / NSPAT;
    const int oy   = bx - ox * NSPAT;

    // ---- stage 1: fetch 18 bitmask rows (one LDG.128 per active lane) ----
    if (lane < W18) {
        int i = lane / 9, rem = lane - i * 9, kx = rem / 3, ky = rem - kx * 3;
        size_t rowidx = (((size_t)b * 2 + i) * 64 + (2 * ox + kx)) * 64 + (2 * oy + ky);
        uint4 v = __ldg((const uint4*)&g_bits[rowidx * 4]);
        *(uint4*)&s_bits[lane * 4] = v;
    }
#pragma unroll
    for (int i = lane; i < 152; i += 32) s_cnt[i] = 0.f;
    __syncwarp();

    // ---- stage 1b: shared-ramp counts: cnt[s+2] = (#spikes at s)/16 ----
#pragma unroll
    for (int seg = 0; seg < 4; ++seg) {
        int c = 0;
#pragma unroll
        for (int w = 0; w < W18; ++w) c += (int)((s_bits[w * 4 + seg] >> lane) & 1u);
        int s = seg * 32 + lane;
        if (s < TIN) s_cnt[s + 2] = (float)c * 0.0625f;
    }
    __syncwarp();

    // ---- per-half: zero grid, scatter events, cumsum + WTA ----
    float* col = s_grid + lane;
    float a1 = 0.f, c1 = 0.f, a2 = 0.f;
    int dep = 0, k = 0;
    int wt0 = -1, wt1 = -1, wt2 = -1, wt3 = -1;
    int wc0 = 0, wc1 = 0, wc2 = 0, wc3 = 0;

#pragma unroll 1
    for (int h = 0; h < 2; ++h) {
        const int lo = h * HROWS;

        // zero half grid
        {
            float4 z4 = make_float4(0.f, 0.f, 0.f, 0.f);
#pragma unroll
            for (int i = lane; i < HROWS * COUT / 4; i += 32) s_grid4[i] = z4;
        }
        __syncwarp();

        // per-seg spike filter: half0 needs s<=73, half1 needs s>=25
        unsigned segmask[4];
        if (h == 0) {
            segmask[0] = 0xffffffffu; segmask[1] = 0xffffffffu;
            segmask[2] = 0x000003ffu; segmask[3] = 0u;          // s<=73
        } else {
            segmask[0] = 0xfe000000u;                           // s>=25
            segmask[1] = 0xffffffffu; segmask[2] = 0xffffffffu;
            segmask[3] = 0xffffffffu;
        }

        // scatter hinge events (lane-private smem column, deterministic order)
#pragma unroll 1
        for (int w = 0; w < W18; ++w) {
            float4 ev = __ldg(&g_t1[w * 32 + lane]);
            int    nn = __ldg(&g_t2[w * 32 + lane]);
            int n1 = nn & 0xffff;
            int n2 = nn >> 16;
#pragma unroll
            for (int seg = 0; seg < 4; ++seg) {
                unsigned m = s_bits[w * 4 + seg] & segmask[seg];
                int sbase = seg * 32 + 1 - lo;       // r - lo for bit 0
                while (m) {
                    int bp = __ffs((int)m) - 1;
                    m &= m - 1;
                    int r1 = sbase + bp + n1;        // rel row of hinge-1 ev A
                    int r2 = sbase + bp + n2;        // rel row of hinge-2 ev A
                    if ((unsigned)r1 < (unsigned)HROWS)       col[r1 * 32]       += ev.x;
                    if ((unsigned)(r1 + 1) < (unsigned)HROWS) col[(r1 + 1) * 32] += ev.y;
                    if ((unsigned)r2 < (unsigned)HROWS)       col[r2 * 32]       += ev.z;
                    if ((unsigned)(r2 + 1) < (unsigned)HROWS) col[(r2 + 1) * 32] += ev.w;
                }
            }
        }
        __syncwarp();

        // double cumsum + ballot-gated WTA over this half's t range
        const int tend = (h == 0) ? HROWS : TOUT;
#pragma unroll 1
        for (int t = lo; t < tend; ++t) {
            float v = s_grid[(t - lo) * 32 + lane] + s_cnt[t];
            kadd(a1, c1, v);
            a2 += (a1 + c1);
            if (dep == 0) {
                unsigned fm = __ballot_sync(0xffffffffu, a2 > THETA);
                if (fm) {
                    float bv = a2; int bi = lane;
#pragma unroll
                    for (int off = 16; off; off >>= 1) {
                        float ov = __shfl_xor_sync(0xffffffffu, bv, off);
                        int   oi = __shfl_xor_sync(0xffffffffu, bi, off);
                        if (ov > bv || (ov == bv && oi < bi)) { bv = ov; bi = oi; }
                    }
                    if      (k == 0) { wt0 = t; wc0 = bi; }
                    else if (k == 1) { wt1 = t; wc1 = bi; }
                    else if (k == 2) { wt2 = t; wc2 = bi; }
                    else             { wt3 = t; wc3 = bi; }
                    ++k;
                    dep = KS;
                }
            }
            dep = dep > 0 ? dep - 1 : 0;
        }
        __syncwarp();
    }

    // ---- output: every element written, coalesced 128B per (oc, q) ----
#pragma unroll
    for (int q = 0; q < 5; ++q) {
        int t = q * 32 + lane;
        if (t < TOUT) {
            int wv = -1;
            if (t == wt0) wv = wc0;
            if (t == wt1) wv = wc1;
            if (t == wt2) wv = wc2;
            if (t == wt3) wv = wc3;
            float* obase = out + ((size_t)b * 32 * (NSPAT * NSPAT) + bx) * TOUT + t;
#pragma unroll 1
            for (int oc = 0; oc < 32; ++oc)
                obase[(size_t)oc * (NSPAT * NSPAT) * TOUT] = (wv == oc) ? 1.f : 0.f;
        }
    }
}

extern "C" void kernel_launch(void* const* d_in, const int* in_sizes, int n_in,
                              void* d_out, int out_size) {
    const float* spikes = (const float*)d_in[0];
    const float* weight = (const float*)d_in[1];
    if (n_in >= 2 && in_sizes[0] == 576) {     // defensive input identification
        spikes = (const float*)d_in[1];
        weight = (const float*)d_in[0];
    }

    evt_precompute<<<3, 192>>>(weight);
    binarize_kernel<<<16 * 2 * 64 * 64 / 8, 256>>>(spikes);

    dim3 grid(NSPAT * NSPAT, 16);   // (n, batch)
    wta_kernel<<<grid, 32>>>((float*)d_out);
}

// round 9
// speedup vs baseline: 1.1263x; 1.1029x over previous
#include <cuda_runtime.h>
#include <cstdint>
#include <cstddef>

// ---------------------------------------------------------------------------
// Spiking conv + WTA, Round 9: canonicalized (collision-free) event quads +
// batched clamp-to-dump scatter (de-serialized smem RMW), 76-row x 2-pass
// delta^2 grid, binarized input, registerized WTA records.
// One 32-thread CTA per (b,ox,oy); lane = output channel.
//   r(tau) = tau/16 - (3/32) relu(tau-16w) + (1/32) relu(tau-48w)   (exact)
// ---------------------------------------------------------------------------

#define COUT   32
#define W18    18
#define KS     48
#define TIN    100
#define TOUT   149
#define NSPAT  31
#define THETA  5.4f
#define HROWS  76          // live grid rows per pass
#define GROWS  77          // +1 dump row for clamped events

// event tables, layout [w][o]
__device__ float4   g_t1[W18 * COUT];   // canonical event values v0..v3
__device__ int      g_t2[W18 * COUT];   // packed row offsets r0..r3 (8b each)
__device__ unsigned g_bits[16 * 2 * 64 * 64 * 4];   // spike bitmasks, 2 MB

__global__ void evt_precompute(const float* __restrict__ weight) {
    int idx = blockIdx.x * blockDim.x + threadIdx.x;
    if (idx >= W18 * COUT) return;
    int o = idx & 31;
    int w = idx >> 5;
    double wv = (double)weight[o * W18 + w];

    double p1 = 16.0 * wv;  int n1 = (int)floor(p1) + 1;  double f1 = (double)n1 - p1;
    double p2 = 48.0 * wv;  int n2 = (int)floor(p2) + 1;  double f2 = (double)n2 - p2;
    const double c1 = -3.0 / 32.0, c2 = 1.0 / 32.0;
    double e0 = c1 * f1, e1 = c1 * (1.0 - f1);
    double e2 = c2 * f2, e3 = c2 * (1.0 - f2);

    // canonical quad: strictly increasing distinct rows (merge collisions)
    int r0, r1, r2, r3; double v0, v1, v2, v3;
    if (n2 - n1 >= 2)      { r0=n1; r1=n1+1; r2=n2;   r3=n2+1; v0=e0;    v1=e1;    v2=e2;  v3=e3;  }
    else if (n2 == n1 + 1) { r0=n1; r1=n1+1; r2=n1+2; r3=n1+3; v0=e0;    v1=e1+e2; v2=e3;  v3=0.0; }
    else                   { r0=n1; r1=n1+1; r2=n1+2; r3=n1+3; v0=e0+e2; v1=e1+e3; v2=0.0; v3=0.0; }

    g_t1[idx] = make_float4((float)v0, (float)v1, (float)v2, (float)v3);
    g_t2[idx] = r0 | (r1 << 8) | (r2 << 16) | (r3 << 24);
}

__global__ __launch_bounds__(256)
void binarize_kernel(const float* __restrict__ xin) {
    int wg   = (blockIdx.x * blockDim.x + threadIdx.x) >> 5;
    int lane = threadIdx.x & 31;
    if (wg >= 16 * 2 * 64 * 64) return;
    const float* row = xin + (size_t)wg * TIN;
    unsigned m[4];
#pragma unroll
    for (int seg = 0; seg < 4; ++seg) {
        int t = seg * 32 + lane;
        float v = (t < TIN) ? __ldg(row + t) : 0.f;
        m[seg] = __ballot_sync(0xffffffffu, v != 0.f);
    }
    if (lane == 0)
        *(uint4*)&g_bits[(size_t)wg * 4] = make_uint4(m[0], m[1], m[2], m[3]);
}

// Neumaier compensated add: s += v, compensation c
__device__ __forceinline__ void kadd(float& s, float& c, float v) {
    float t = s + v;
    float e = (fabsf(s) >= fabsf(v)) ? ((s - t) + v) : ((v - t) + s);
    c += e;
    s = t;
}

__global__ __launch_bounds__(32)
void wta_kernel(float* __restrict__ out) {
    __shared__ float4                 s_grid4[GROWS * COUT / 4]; // 9856 B reused
    __shared__ float                  s_cnt[152];                // ramp d2
    __shared__ __align__(16) unsigned s_bits[72];                // 18 rows x 4

    float* s_grid = (float*)s_grid4;

    const int lane = threadIdx.x;
    const int bx   = blockIdx.x;                     // n = ox*31 + oy
    const int b    = blockIdx.y;
    const int ox   = bx / NSPAT;
    const int oy   = bx - ox * NSPAT;

    // ---- stage 1: fetch 18 bitmask rows (one LDG.128 per active lane) ----
    if (lane < W18) {
        int i = lane / 9, rem = lane - i * 9, kx = rem / 3, ky = rem - kx * 3;
        size_t rowidx = (((size_t)b * 2 + i) * 64 + (2 * ox + kx)) * 64 + (2 * oy + ky);
        uint4 v = __ldg((const uint4*)&g_bits[rowidx * 4]);
        *(uint4*)&s_bits[lane * 4] = v;
    }
#pragma unroll
    for (int i = lane; i < 152; i += 32) s_cnt[i] = 0.f;
    __syncwarp();

    // ---- stage 1b: shared-ramp counts: cnt[s+2] = (#spikes at s)/16 ----
#pragma unroll
    for (int seg = 0; seg < 4; ++seg) {
        int c = 0;
#pragma unroll
        for (int w = 0; w < W18; ++w) c += (int)((s_bits[w * 4 + seg] >> lane) & 1u);
        int s = seg * 32 + lane;
        if (s < TIN) s_cnt[s + 2] = (float)c * 0.0625f;
    }
    __syncwarp();

    // ---- per-half: zero grid, scatter events, cumsum + WTA ----
    float* col = s_grid + lane;
    float a1 = 0.f, c1 = 0.f, a2 = 0.f;
    int dep = 0, k = 0;
    int wt0 = -1, wt1 = -1, wt2 = -1, wt3 = -1;
    int wc0 = 0, wc1 = 0, wc2 = 0, wc3 = 0;

#pragma unroll 1
    for (int h = 0; h < 2; ++h) {
        const int lo = h * HROWS;

        // zero grid (incl. dump row)
        {
            float4 z4 = make_float4(0.f, 0.f, 0.f, 0.f);
#pragma unroll
            for (int i = lane; i < GROWS * COUT / 4; i += 32) s_grid4[i] = z4;
        }
        __syncwarp();

        // per-seg spike prefilter (pure optimization; clamp is the guard):
        // half0 needs s<=73, half1 needs s>=25
        unsigned segmask[4];
        if (h == 0) {
            segmask[0] = 0xffffffffu; segmask[1] = 0xffffffffu;
            segmask[2] = 0x000003ffu; segmask[3] = 0u;
        } else {
            segmask[0] = 0xfe000000u;
            segmask[1] = 0xffffffffu; segmask[2] = 0xffffffffu;
            segmask[3] = 0xffffffffu;
        }

        // scatter canonical event quads: batched LDSx4 / FADDx4 / STSx4,
        // out-of-window rows clamped to dump row (HROWS).
#pragma unroll 1
        for (int w = 0; w < W18; ++w) {
            float4 ev = __ldg(&g_t1[w * 32 + lane]);
            int    pk = __ldg(&g_t2[w * 32 + lane]);
            int o0 = pk & 255;
            int o1 = (pk >> 8) & 255;
            int o2 = (pk >> 16) & 255;
            int o3 = ((unsigned)pk) >> 24;
#pragma unroll
            for (int seg = 0; seg < 4; ++seg) {
                unsigned m = s_bits[w * 4 + seg] & segmask[seg];
                int sbase = seg * 32 + 1 - lo;       // s+1-lo for bit 0
                while (m) {
                    int bp = __ffs((int)m) - 1;
                    m &= m - 1;
                    int r = sbase + bp;
                    unsigned u0 = min((unsigned)(r + o0), (unsigned)HROWS);
                    unsigned u1 = min((unsigned)(r + o1), (unsigned)HROWS);
                    unsigned u2 = min((unsigned)(r + o2), (unsigned)HROWS);
                    unsigned u3 = min((unsigned)(r + o3), (unsigned)HROWS);
                    float g0 = col[u0 * 32];
                    float g1 = col[u1 * 32];
                    float g2 = col[u2 * 32];
                    float g3 = col[u3 * 32];
                    g0 += ev.x; g1 += ev.y; g2 += ev.z; g3 += ev.w;
                    col[u0 * 32] = g0;
                    col[u1 * 32] = g1;
                    col[u2 * 32] = g2;
                    col[u3 * 32] = g3;
                }
            }
        }
        __syncwarp();

        // double cumsum + ballot-gated WTA over this half's t range
        const int tend = (h == 0) ? HROWS : TOUT;
#pragma unroll 1
        for (int t = lo; t < tend; ++t) {
            float v = s_grid[(t - lo) * 32 + lane] + s_cnt[t];
            kadd(a1, c1, v);
            a2 += (a1 + c1);
            if (dep == 0) {
                unsigned fm = __ballot_sync(0xffffffffu, a2 > THETA);
                if (fm) {
                    float bv = a2; int bi = lane;
#pragma unroll
                    for (int off = 16; off; off >>= 1) {
                        float ov = __shfl_xor_sync(0xffffffffu, bv, off);
                        int   oi = __shfl_xor_sync(0xffffffffu, bi, off);
                        if (ov > bv || (ov == bv && oi < bi)) { bv = ov; bi = oi; }
                    }
                    if      (k == 0) { wt0 = t; wc0 = bi; }
                    else if (k == 1) { wt1 = t; wc1 = bi; }
                    else if (k == 2) { wt2 = t; wc2 = bi; }
                    else             { wt3 = t; wc3 = bi; }
                    ++k;
                    dep = KS;
                }
            }
            dep = dep > 0 ? dep - 1 : 0;
        }
        __syncwarp();
    }

    // ---- output: every element written, coalesced 128B per (oc, q) ----
#pragma unroll
    for (int q = 0; q < 5; ++q) {
        int t = q * 32 + lane;
        if (t < TOUT) {
            int wv = -1;
            if (t == wt0) wv = wc0;
            if (t == wt1) wv = wc1;
            if (t == wt2) wv = wc2;
            if (t == wt3) wv = wc3;
            float* obase = out + ((size_t)b * 32 * (NSPAT * NSPAT) + bx) * TOUT + t;
#pragma unroll 1
            for (int oc = 0; oc < 32; ++oc)
                obase[(size_t)oc * (NSPAT * NSPAT) * TOUT] = (wv == oc) ? 1.f : 0.f;
        }
    }
}

extern "C" void kernel_launch(void* const* d_in, const int* in_sizes, int n_in,
                              void* d_out, int out_size) {
    const float* spikes = (const float*)d_in[0];
    const float* weight = (const float*)d_in[1];
    if (n_in >= 2 && in_sizes[0] == 576) {     // defensive input identification
        spikes = (const float*)d_in[1];
        weight = (const float*)d_in[0];
    }

    evt_precompute<<<3, 192>>>(weight);
    binarize_kernel<<<16 * 2 * 64 * 64 / 8, 256>>>(spikes);

    dim3 grid(NSPAT * NSPAT, 16);   // (n, batch)
    wta_kernel<<<grid, 32>>>((float*)d_out);
}

// round 10
// speedup vs baseline: 1.1970x; 1.0628x over previous
#include <cuda_runtime.h>
#include <cstdint>
#include <cstddef>

// ---------------------------------------------------------------------------
// Spiking conv + WTA, Round 10: 22-CTA/SM smem budget, Kahan slope,
// software-pipelined cumsum, canonical collision-free event quads with
// clamp-to-dump scatter. One 32-thread CTA per (b,ox,oy); lane = channel.
//   r(tau) = tau/16 - (3/32) relu(tau-16w) + (1/32) relu(tau-48w)   (exact)
// ---------------------------------------------------------------------------

#define COUT   32
#define W18    18
#define KS     48
#define TIN    100
#define TOUT   149
#define NSPAT  31
#define THETA  5.4f
#define HROWS  76          // live grid rows per pass
#define GROWS  77          // +1 dump row for clamped / prefetch reads
#define CNTSZ  112         // s_cnt entries (index >101 provably zero)

// event tables, layout [w][o]
__device__ float4   g_t1[W18 * COUT];   // canonical event values v0..v3
__device__ int      g_t2[W18 * COUT];   // packed row offsets r0..r3 (8b each)
__device__ unsigned g_bits[16 * 2 * 64 * 64 * 4];   // spike bitmasks, 2 MB

__global__ void evt_precompute(const float* __restrict__ weight) {
    int idx = blockIdx.x * blockDim.x + threadIdx.x;
    if (idx >= W18 * COUT) return;
    int o = idx & 31;
    int w = idx >> 5;
    double wv = (double)weight[o * W18 + w];

    double p1 = 16.0 * wv;  int n1 = (int)floor(p1) + 1;  double f1 = (double)n1 - p1;
    double p2 = 48.0 * wv;  int n2 = (int)floor(p2) + 1;  double f2 = (double)n2 - p2;
    const double c1 = -3.0 / 32.0, c2 = 1.0 / 32.0;
    double e0 = c1 * f1, e1 = c1 * (1.0 - f1);
    double e2 = c2 * f2, e3 = c2 * (1.0 - f2);

    // canonical quad: strictly increasing distinct rows (merge collisions)
    int r0, r1, r2, r3; double v0, v1, v2, v3;
    if (n2 - n1 >= 2)      { r0=n1; r1=n1+1; r2=n2;   r3=n2+1; v0=e0;    v1=e1;    v2=e2;  v3=e3;  }
    else if (n2 == n1 + 1) { r0=n1; r1=n1+1; r2=n1+2; r3=n1+3; v0=e0;    v1=e1+e2; v2=e3;  v3=0.0; }
    else                   { r0=n1; r1=n1+1; r2=n1+2; r3=n1+3; v0=e0+e2; v1=e1+e3; v2=0.0; v3=0.0; }

    g_t1[idx] = make_float4((float)v0, (float)v1, (float)v2, (float)v3);
    g_t2[idx] = r0 | (r1 << 8) | (r2 << 16) | (r3 << 24);
}

__global__ __launch_bounds__(256)
void binarize_kernel(const float* __restrict__ xin) {
    int wg   = (blockIdx.x * blockDim.x + threadIdx.x) >> 5;
    int lane = threadIdx.x & 31;
    if (wg >= 16 * 2 * 64 * 64) return;
    const float* row = xin + (size_t)wg * TIN;
    unsigned m[4];
#pragma unroll
    for (int seg = 0; seg < 4; ++seg) {
        int t = seg * 32 + lane;
        float v = (t < TIN) ? __ldg(row + t) : 0.f;
        m[seg] = __ballot_sync(0xffffffffu, v != 0.f);
    }
    if (lane == 0)
        *(uint4*)&g_bits[(size_t)wg * 4] = make_uint4(m[0], m[1], m[2], m[3]);
}

__global__ __launch_bounds__(32)
void wta_kernel(float* __restrict__ out) {
    __shared__ float4                 s_grid4[GROWS * COUT / 4]; // 9856 B reused
    __shared__ float                  s_cnt[CNTSZ];              // ramp d2
    __shared__ __align__(16) unsigned s_bits[72];                // 18 rows x 4

    float* s_grid = (float*)s_grid4;

    const int lane = threadIdx.x;
    const int bx   = blockIdx.x;                     // n = ox*31 + oy
    const int b    = blockIdx.y;
    const int ox   = bx / NSPAT;
    const int oy   = bx - ox * NSPAT;

    // ---- stage 1: fetch 18 bitmask rows (one LDG.128 per active lane) ----
    if (lane < W18) {
        int i = lane / 9, rem = lane - i * 9, kx = rem / 3, ky = rem - kx * 3;
        size_t rowidx = (((size_t)b * 2 + i) * 64 + (2 * ox + kx)) * 64 + (2 * oy + ky);
        uint4 v = __ldg((const uint4*)&g_bits[rowidx * 4]);
        *(uint4*)&s_bits[lane * 4] = v;
    }
#pragma unroll
    for (int i = lane; i < CNTSZ; i += 32) s_cnt[i] = 0.f;
    __syncwarp();

    // ---- stage 1b: shared-ramp counts: cnt[s+2] = (#spikes at s)/16 ----
#pragma unroll
    for (int seg = 0; seg < 4; ++seg) {
        int c = 0;
#pragma unroll
        for (int w = 0; w < W18; ++w) c += (int)((s_bits[w * 4 + seg] >> lane) & 1u);
        int s = seg * 32 + lane;
        if (s < TIN) s_cnt[s + 2] = (float)c * 0.0625f;
    }
    __syncwarp();

    // ---- per-half: zero grid, scatter events, cumsum + WTA ----
    float* col = s_grid + lane;
    float a1 = 0.f, c1 = 0.f, a2 = 0.f;
    int dep = 0, k = 0;
    int wt0 = -1, wt1 = -1, wt2 = -1, wt3 = -1;
    int wc0 = 0, wc1 = 0, wc2 = 0, wc3 = 0;

#pragma unroll 1
    for (int h = 0; h < 2; ++h) {
        const int lo = h * HROWS;

        // zero grid (incl. dump row)
        {
            float4 z4 = make_float4(0.f, 0.f, 0.f, 0.f);
#pragma unroll
            for (int i = lane; i < GROWS * COUT / 4; i += 32) s_grid4[i] = z4;
        }
        __syncwarp();

        // per-seg spike prefilter (clamp is the correctness guard):
        // half0 needs s<=73, half1 needs s>=25
        unsigned segmask[4];
        if (h == 0) {
            segmask[0] = 0xffffffffu; segmask[1] = 0xffffffffu;
            segmask[2] = 0x000003ffu; segmask[3] = 0u;
        } else {
            segmask[0] = 0xfe000000u;
            segmask[1] = 0xffffffffu; segmask[2] = 0xffffffffu;
            segmask[3] = 0xffffffffu;
        }

        // scatter canonical event quads: batched LDSx4 / FADDx4 / STSx4,
        // out-of-window rows clamped to dump row (HROWS).
#pragma unroll 2
        for (int w = 0; w < W18; ++w) {
            float4 ev = __ldg(&g_t1[w * 32 + lane]);
            int    pk = __ldg(&g_t2[w * 32 + lane]);
            int o0 = pk & 255;
            int o1 = (pk >> 8) & 255;
            int o2 = (pk >> 16) & 255;
            int o3 = ((unsigned)pk) >> 24;
#pragma unroll
            for (int seg = 0; seg < 4; ++seg) {
                unsigned m = s_bits[w * 4 + seg] & segmask[seg];
                int sbase = seg * 32 + 1 - lo;       // s+1-lo for bit 0
                while (m) {
                    int bp = __ffs((int)m) - 1;
                    m &= m - 1;
                    int r = sbase + bp;
                    unsigned u0 = min((unsigned)(r + o0), (unsigned)HROWS);
                    unsigned u1 = min((unsigned)(r + o1), (unsigned)HROWS);
                    unsigned u2 = min((unsigned)(r + o2), (unsigned)HROWS);
                    unsigned u3 = min((unsigned)(r + o3), (unsigned)HROWS);
                    float g0 = col[u0 * 32];
                    float g1 = col[u1 * 32];
                    float g2 = col[u2 * 32];
                    float g3 = col[u3 * 32];
                    g0 += ev.x; g1 += ev.y; g2 += ev.z; g3 += ev.w;
                    col[u0 * 32] = g0;
                    col[u1 * 32] = g1;
                    col[u2 * 32] = g2;
                    col[u3 * 32] = g3;
                }
            }
        }
        __syncwarp();

        // double cumsum + ballot-gated WTA, software-pipelined row fetch.
        // Kahan compensation: corrected slope = a1 - c1.
        const int tend = (h == 0) ? HROWS : TOUT;
        float v = s_grid[lane] + s_cnt[min(lo, 108)];
#pragma unroll 1
        for (int t = lo; t < tend; ++t) {
            // prefetch next row (edge reads land in dump row / zero cnt tail)
            float vn = s_grid[(t + 1 - lo) * 32 + lane] + s_cnt[min(t + 1, 108)];
            float y  = v - c1;
            float tt = a1 + y;
            c1 = (tt - a1) - y;
            a1 = tt;
            a2 += (a1 - c1);
            if (dep == 0) {
                unsigned fm = __ballot_sync(0xffffffffu, a2 > THETA);
                if (fm) {
                    float bv = a2; int bi = lane;
#pragma unroll
                    for (int off = 16; off; off >>= 1) {
                        float ov = __shfl_xor_sync(0xffffffffu, bv, off);
                        int   oi = __shfl_xor_sync(0xffffffffu, bi, off);
                        if (ov > bv || (ov == bv && oi < bi)) { bv = ov; bi = oi; }
                    }
                    if      (k == 0) { wt0 = t; wc0 = bi; }
                    else if (k == 1) { wt1 = t; wc1 = bi; }
                    else if (k == 2) { wt2 = t; wc2 = bi; }
                    else             { wt3 = t; wc3 = bi; }
                    ++k;
                    dep = KS;
                }
            }
            dep = dep > 0 ? dep - 1 : 0;
            v = vn;
        }
        __syncwarp();
    }

    // ---- output: every element written, coalesced 128B per (oc, q) ----
#pragma unroll
    for (int q = 0; q < 5; ++q) {
        int t = q * 32 + lane;
        if (t < TOUT) {
            int wv = -1;
            if (t == wt0) wv = wc0;
            if (t == wt1) wv = wc1;
            if (t == wt2) wv = wc2;
            if (t == wt3) wv = wc3;
            float* obase = out + ((size_t)b * 32 * (NSPAT * NSPAT) + bx) * TOUT + t;
#pragma unroll 1
            for (int oc = 0; oc < 32; ++oc)
                obase[(size_t)oc * (NSPAT * NSPAT) * TOUT] = (wv == oc) ? 1.f : 0.f;
        }
    }
}

extern "C" void kernel_launch(void* const* d_in, const int* in_sizes, int n_in,
                              void* d_out, int out_size) {
    const float* spikes = (const float*)d_in[0];
    const float* weight = (const float*)d_in[1];
    if (n_in >= 2 && in_sizes[0] == 576) {     // defensive input identification
        spikes = (const float*)d_in[1];
        weight = (const float*)d_in[0];
    }

    evt_precompute<<<3, 192>>>(weight);
    binarize_kernel<<<16 * 2 * 64 * 64 / 8, 256>>>(spikes);

    dim3 grid(NSPAT * NSPAT, 16);   // (n, batch)
    wta_kernel<<<grid, 32>>>((float*)d_out);
}